// round 1
// baseline (speedup 1.0000x reference)
#include <cuda_runtime.h>
#include <cstdint>

// ---------------------------------------------------------------------------
// MemoryAttention: fused RBF top-k retrieval + softmax gather + gate.
//   B*T = 8192 queries, N = 32768 centers, D_KEY = 64, D_VALUE = 128,
//   D_EMO = 4, D_MODEL = 256, K = 32.
//
// Plan:
//   kernel 1: hm2[c] = 0.5 * ||mu_c||^2
//   kernel 2: per CTA, 32 queries. Stream centers in chunks of 128 through a
//             double-buffered cp.async smem pipeline. Register-blocked GEMM
//             (4q x 4c per thread) using packed fma.rn.f32x2 (full-rate fp32
//             on sm_103a; scalar FFMA is half-rate). Warp-resident top-32
//             (one candidate per lane, ballot+min-threshold streaming select).
//             Epilogue: softmax over 32 scores, weighted V/E gather, gate.
// ---------------------------------------------------------------------------

#define FULLMASK 0xffffffffu

static __device__ float g_hm2[32768];

constexpr int NQ  = 8192;     // B*T
constexpr int NC  = 32768;    // centers
constexpr int DK  = 64;       // key dim
constexpr int QT  = 32;       // queries per CTA
constexpr int CT  = 128;      // centers per chunk
constexpr int NCHUNK = NC / CT;
constexpr int MUS = 68;       // smem row stride (floats) for mu/q tiles (pad for banks)
constexpr int SSTR = 132;     // smem score row stride

constexpr int RV_OFF = 0;
constexpr int RE_OFF = NQ * 128;            // 1048576
constexpr int G_OFF  = RE_OFF + NQ * 4;     // 1081344

// smem layout (floats)
constexpr int OFF_Q   = 0;                  // 32*68      = 2176
constexpr int OFF_MU  = OFF_Q + QT * MUS;   // 2*128*68   = 17408
constexpr int OFF_HM2 = OFF_MU + 2 * CT * MUS;  // 2*128  = 256
constexpr int OFF_S   = OFF_HM2 + 2 * CT;   // 32*132     = 4224
constexpr int OFF_TV  = OFF_S + QT * SSTR;  // 32*32      = 1024
constexpr int OFF_TI  = OFF_TV + QT * 32;   // 32*32      = 1024
constexpr int SMEM_FLOATS = OFF_TI + QT * 32;   // 26112 floats = 104448 B

__global__ void hm2_kernel(const float* __restrict__ mu) {
    int c = blockIdx.x * 256 + threadIdx.x;   // grid 128 x 256 = 32768 exactly
    const float4* r = reinterpret_cast<const float4*>(mu) + (size_t)c * 16;
    float s = 0.f;
#pragma unroll
    for (int j = 0; j < 16; j++) {
        float4 v = r[j];
        s += v.x * v.x + v.y * v.y + v.z * v.z + v.w * v.w;
    }
    g_hm2[c] = 0.5f * s;
}

// streaming warp top-32 insert: one candidate per lane, thr = current min
__device__ __forceinline__ void topk_insert(float v, int idx, int lane,
                                            float& cv, int& ci, float& thr) {
    unsigned m = __ballot_sync(FULLMASK, v > thr);
    while (m) {
        int src = __ffs(m) - 1;
        m &= m - 1;
        float nv = __shfl_sync(FULLMASK, v, src);
        int   ni = __shfl_sync(FULLMASK, idx, src);
        // argmin over candidates (deterministic tie-break -> all lanes agree)
        float mv = cv; int ml = lane;
#pragma unroll
        for (int off = 16; off; off >>= 1) {
            float ov = __shfl_xor_sync(FULLMASK, mv, off);
            int   ol = __shfl_xor_sync(FULLMASK, ml, off);
            if (ov < mv || (ov == mv && ol < ml)) { mv = ov; ml = ol; }
        }
        if (nv > mv) {
            if (lane == ml) { cv = nv; ci = ni; }
            float t = cv;
#pragma unroll
            for (int off = 16; off; off >>= 1)
                t = fminf(t, __shfl_xor_sync(FULLMASK, t, off));
            thr = t;
        }
    }
}

__global__ __launch_bounds__(256, 2)
void ma_kernel(const float* __restrict__ x,
               const float* __restrict__ q_tilde,
               const float* __restrict__ g_prior,
               const float* __restrict__ mu,
               const float* __restrict__ V,
               const float* __restrict__ E,
               const float* __restrict__ sig,
               const float* __restrict__ Wg,
               const float* __restrict__ Wgb,
               const float* __restrict__ gpw,
               float* __restrict__ out) {
    extern __shared__ float sm[];
    float* sQ   = sm + OFF_Q;
    float* sMu  = sm + OFF_MU;
    float* sHm2 = sm + OFF_HM2;
    float* sS   = sm + OFF_S;
    float* sTopV = sm + OFF_TV;
    int*   sTopI = reinterpret_cast<int*>(sm + OFF_TI);

    const int tid  = threadIdx.x;
    const int lane = tid & 31;
    const int wid  = tid >> 5;
    const int qx   = tid & 7;    // q sub-index  (8)
    const int cy   = tid >> 3;   // c sub-index  (32)
    const int q0   = blockIdx.x * QT;

    // ---- stage Q tile: sQ[q][k], row stride 68 ----
#pragma unroll
    for (int j = 0; j < 8; j++) {
        int idx = tid + 256 * j;          // 0..2047
        int q = idx >> 6, k = idx & 63;
        sQ[q * MUS + k] = q_tilde[(size_t)(q0 + q) * DK + k];
    }

    const uint32_t smuA = (uint32_t)__cvta_generic_to_shared(sMu);
    const uint32_t shmA = (uint32_t)__cvta_generic_to_shared(sHm2);

    auto issue_chunk = [&](int chunk) {
        int buf = chunk & 1;
        uint32_t mdst = smuA + (uint32_t)(buf * (CT * MUS * 4));
        const float* src = mu + (size_t)chunk * CT * DK;
#pragma unroll
        for (int j = 0; j < 8; j++) {
            int idx = tid + 256 * j;      // 0..2047 : 128 rows x 16 float4
            int c = idx >> 4, kq = idx & 15;
            asm volatile("cp.async.cg.shared.global [%0], [%1], 16;\n"
                         :: "r"(mdst + (uint32_t)((c * MUS + kq * 4) * 4)),
                            "l"(src + c * DK + kq * 4));
        }
        if (tid < 32) {
            asm volatile("cp.async.cg.shared.global [%0], [%1], 16;\n"
                         :: "r"(shmA + (uint32_t)(buf * CT * 4 + tid * 16)),
                            "l"(g_hm2 + chunk * CT + tid * 4));
        }
        asm volatile("cp.async.commit_group;\n");
    };

    issue_chunk(0);

    // warp-resident top-32 state: 4 queries per warp
    float cv[4]; int ci[4]; float thr[4];
#pragma unroll
    for (int r = 0; r < 4; r++) { cv[r] = -INFINITY; ci[r] = 0; thr[r] = -INFINITY; }

    for (int ch = 0; ch < NCHUNK; ++ch) {
        if (ch + 1 < NCHUNK) {
            issue_chunk(ch + 1);
            asm volatile("cp.async.wait_group 1;\n");
        } else {
            asm volatile("cp.async.wait_group 0;\n");
        }
        __syncthreads();   // buf[ch&1] + sQ visible; prior selection done reading sS

        const float* mb = sMu + (ch & 1) * (CT * MUS);
        const float* hb = sHm2 + (ch & 1) * CT;

        // ---- register-blocked GEMM: 4q x 4c per thread, f32x2 packed FMA ----
        unsigned long long acc[4][4];
#pragma unroll
        for (int a = 0; a < 4; a++)
#pragma unroll
            for (int b = 0; b < 4; b++) acc[a][b] = 0ull;

#pragma unroll
        for (int k = 0; k < DK; k += 4) {
            ulonglong2 qv[4], cvv[4];
#pragma unroll
            for (int a = 0; a < 4; a++)
                qv[a] = *reinterpret_cast<const ulonglong2*>(sQ + (qx + 8 * a) * MUS + k);
#pragma unroll
            for (int b = 0; b < 4; b++)
                cvv[b] = *reinterpret_cast<const ulonglong2*>(mb + (cy + 32 * b) * MUS + k);
#pragma unroll
            for (int a = 0; a < 4; a++)
#pragma unroll
                for (int b = 0; b < 4; b++) {
                    asm("fma.rn.f32x2 %0, %1, %2, %0;"
                        : "+l"(acc[a][b]) : "l"(qv[a].x), "l"(cvv[b].x));
                    asm("fma.rn.f32x2 %0, %1, %2, %0;"
                        : "+l"(acc[a][b]) : "l"(qv[a].y), "l"(cvv[b].y));
                }
        }

        // scores: s' = q.mu - 0.5*||mu||^2   (selection metric; softmax-equivalent)
#pragma unroll
        for (int a = 0; a < 4; a++)
#pragma unroll
            for (int b = 0; b < 4; b++) {
                float2 f = *reinterpret_cast<float2*>(&acc[a][b]);
                float s = f.x + f.y - hb[cy + 32 * b];
                sS[(qx + 8 * a) * SSTR + (cy + 32 * b)] = s;
            }
        __syncthreads();

        // ---- streaming top-32 selection: warp w owns queries 4w..4w+3 ----
        int base = ch * CT;
#pragma unroll
        for (int r = 0; r < 4; r++) {
            int q = 4 * wid + r;
            const float* row = sS + q * SSTR;
#pragma unroll
            for (int s = 0; s < 4; s++) {
                float v = row[lane + 32 * s];
                int idx = base + lane + 32 * s;
                topk_insert(v, idx, lane, cv[r], ci[r], thr[r]);
            }
        }
        // next iteration's first __syncthreads() protects sS and smem buffers
    }

    // ---- publish top-32 per query ----
#pragma unroll
    for (int r = 0; r < 4; r++) {
        int q = 4 * wid + r;
        sTopV[q * 32 + lane] = cv[r];
        sTopI[q * 32 + lane] = ci[r];
    }
    __syncthreads();

    const float sigma  = sig[0];
    const float inv_s2 = 1.f / (sigma * sigma);
    const float bgate  = Wgb[0];
    const float gw     = gpw[0];

    float* myW = sS + wid * 64;                 // per-warp scratch (reuse sS)
    int*   myI = reinterpret_cast<int*>(myW + 32);

    // ---- epilogue: softmax + gathers + gate. warp w handles q = w + 8*round
#pragma unroll
    for (int round = 0; round < 4; ++round) {
        int q  = wid + 8 * round;
        int qg = q0 + q;

        float sv  = sTopV[q * 32 + lane];
        int   idx = sTopI[q * 32 + lane];
        float s = sv * inv_s2;                  // softmax(score) == softmax(s'/sigma^2)
        float mx = s;
#pragma unroll
        for (int off = 16; off; off >>= 1)
            mx = fmaxf(mx, __shfl_xor_sync(FULLMASK, mx, off));
        float e = __expf(s - mx);
        float se = e;
#pragma unroll
        for (int off = 16; off; off >>= 1)
            se += __shfl_xor_sync(FULLMASK, se, off);
        float wgt = e / se;

        myW[lane] = wgt;
        myI[lane] = idx;
        __syncwarp();

        // r_V: lane owns dims [4*lane, 4*lane+4)
        float4 acc = make_float4(0.f, 0.f, 0.f, 0.f);
#pragma unroll 4
        for (int k = 0; k < 32; k++) {
            float wk = myW[k];
            size_t row = (size_t)myI[k];
            float4 v = reinterpret_cast<const float4*>(V + row * 128)[lane];
            acc.x += wk * v.x; acc.y += wk * v.y;
            acc.z += wk * v.z; acc.w += wk * v.w;
        }

        // r_E (4 dims)
        float re = 0.f;
        if (lane < 4) {
            for (int k = 0; k < 32; k++)
                re += myW[k] * E[(size_t)myI[k] * 4 + lane];
        }

        // gate: sigmoid( x.W1 + rV.W2 + b + gpw * g_prior )
        const float4 wv = reinterpret_cast<const float4*>(Wg + 256)[lane];
        float tot = acc.x * wv.x + acc.y * wv.y + acc.z * wv.z + acc.w * wv.w;
        const float* xq = x + (size_t)qg * 256;
#pragma unroll
        for (int u = 0; u < 8; u++) {
            int t = lane + 32 * u;
            tot += xq[t] * Wg[t];
        }
#pragma unroll
        for (int off = 16; off; off >>= 1)
            tot += __shfl_xor_sync(FULLMASK, tot, off);

        reinterpret_cast<float4*>(out + RV_OFF + (size_t)qg * 128)[lane] = acc;
        if (lane < 4) out[RE_OFF + (size_t)qg * 4 + lane] = re;
        if (lane == 0) {
            float z = tot + bgate + gw * g_prior[qg];
            out[G_OFF + qg] = 1.f / (1.f + __expf(-z));
        }
        __syncwarp();
    }
}

extern "C" void kernel_launch(void* const* d_in, const int* in_sizes, int n_in,
                              void* d_out, int out_size) {
    (void)in_sizes; (void)n_in; (void)out_size;
    const float* x   = (const float*)d_in[0];
    const float* qt  = (const float*)d_in[1];
    const float* gp  = (const float*)d_in[2];
    const float* mu  = (const float*)d_in[3];
    const float* V   = (const float*)d_in[4];
    const float* E   = (const float*)d_in[5];
    const float* sg  = (const float*)d_in[6];
    const float* Wg  = (const float*)d_in[7];
    const float* Wb  = (const float*)d_in[8];
    const float* gw  = (const float*)d_in[9];

    hm2_kernel<<<NC / 256, 256>>>(mu);

    const int smem_bytes = SMEM_FLOATS * 4;
    cudaFuncSetAttribute(ma_kernel, cudaFuncAttributeMaxDynamicSharedMemorySize,
                         smem_bytes);
    ma_kernel<<<NQ / QT, 256, smem_bytes>>>(x, qt, gp, mu, V, E, sg, Wg, Wb, gw,
                                            (float*)d_out);
}

// round 2
// speedup vs baseline: 1.2486x; 1.2486x over previous
#include <cuda_runtime.h>
#include <cstdint>

// ---------------------------------------------------------------------------
// MemoryAttention: fused RBF top-k retrieval + softmax gather + gate.
// R2: selection fused into registers (warp owns its 4 queries' full score
//     rows), redux.sync-based top-32 insert, 1 barrier/chunk, race-free
//     prefetch schedule. GEMM unchanged: packed fma.rn.f32x2, 4q x 4c/thread.
// ---------------------------------------------------------------------------

#define FULLMASK 0xffffffffu

static __device__ float g_hm2[32768];

constexpr int NQ  = 8192;     // B*T
constexpr int NC  = 32768;    // centers
constexpr int DK  = 64;       // key dim
constexpr int QT  = 32;       // queries per CTA
constexpr int CT  = 128;      // centers per chunk
constexpr int NCHUNK = NC / CT;
constexpr int MUS = 68;       // smem row stride (floats), pads banks

constexpr int RV_OFF = 0;
constexpr int RE_OFF = NQ * 128;
constexpr int G_OFF  = RE_OFF + NQ * 4;

// smem layout (floats)
constexpr int OFF_Q   = 0;                       // 32*68  = 2176
constexpr int OFF_MU  = OFF_Q + QT * MUS;        // 2*128*68 = 17408
constexpr int OFF_HM2 = OFF_MU + 2 * CT * MUS;   // 2*128 = 256
constexpr int OFF_TV  = OFF_HM2 + 2 * CT;        // 32*32 = 1024
constexpr int OFF_TI  = OFF_TV + QT * 32;        // 32*32 = 1024
constexpr int OFF_SCR = OFF_TI + QT * 32;        // 8*64  = 512
constexpr int SMEM_FLOATS = OFF_SCR + 8 * 64;    // 22400 floats = 89600 B

__global__ void hm2_kernel(const float* __restrict__ mu) {
    int c = blockIdx.x * 256 + threadIdx.x;
    const float4* r = reinterpret_cast<const float4*>(mu) + (size_t)c * 16;
    float s = 0.f;
#pragma unroll
    for (int j = 0; j < 16; j++) {
        float4 v = r[j];
        s += v.x * v.x + v.y * v.y + v.z * v.z + v.w * v.w;
    }
    g_hm2[c] = 0.5f * s;
}

// order-preserving float <-> uint
__device__ __forceinline__ unsigned fenc(float f) {
    unsigned u = __float_as_uint(f);
    return (u & 0x80000000u) ? ~u : (u | 0x80000000u);
}
__device__ __forceinline__ float fdec(unsigned u) {
    return (u & 0x80000000u) ? __uint_as_float(u & 0x7fffffffu)
                             : __uint_as_float(~u);
}
__device__ __forceinline__ unsigned redux_min_u32(unsigned v) {
    unsigned r;
    asm("redux.sync.min.u32 %0, %1, 0xffffffff;" : "=r"(r) : "r"(v));
    return r;
}

__global__ __launch_bounds__(256, 2)
void ma_kernel(const float* __restrict__ x,
               const float* __restrict__ q_tilde,
               const float* __restrict__ g_prior,
               const float* __restrict__ mu,
               const float* __restrict__ V,
               const float* __restrict__ E,
               const float* __restrict__ sig,
               const float* __restrict__ Wg,
               const float* __restrict__ Wgb,
               const float* __restrict__ gpw,
               float* __restrict__ out) {
    extern __shared__ float sm[];
    float* sQ    = sm + OFF_Q;
    float* sMu   = sm + OFF_MU;
    float* sHm2  = sm + OFF_HM2;
    float* sTopV = sm + OFF_TV;
    int*   sTopI = reinterpret_cast<int*>(sm + OFF_TI);
    float* sScr  = sm + OFF_SCR;

    const int tid  = threadIdx.x;
    const int lane = tid & 31;
    const int wid  = tid >> 5;
    const int q0   = blockIdx.x * QT;

    // ---- stage Q tile: sQ[q][k] ----
#pragma unroll
    for (int j = 0; j < 8; j++) {
        int idx = tid + 256 * j;
        int q = idx >> 6, k = idx & 63;
        sQ[q * MUS + k] = q_tilde[(size_t)(q0 + q) * DK + k];
    }

    const uint32_t smuA = (uint32_t)__cvta_generic_to_shared(sMu);
    const uint32_t shmA = (uint32_t)__cvta_generic_to_shared(sHm2);

    auto issue_chunk = [&](int chunk) {
        int buf = chunk & 1;
        uint32_t mdst = smuA + (uint32_t)(buf * (CT * MUS * 4));
        const float* src = mu + (size_t)chunk * CT * DK;
#pragma unroll
        for (int j = 0; j < 8; j++) {
            int idx = tid + 256 * j;            // 128 rows x 16 float4
            int c = idx >> 4, kq = idx & 15;
            asm volatile("cp.async.cg.shared.global [%0], [%1], 16;\n"
                         :: "r"(mdst + (uint32_t)((c * MUS + kq * 4) * 4)),
                            "l"(src + c * DK + kq * 4));
        }
        if (tid < 32) {
            asm volatile("cp.async.cg.shared.global [%0], [%1], 16;\n"
                         :: "r"(shmA + (uint32_t)(buf * CT * 4 + tid * 16)),
                            "l"(g_hm2 + chunk * CT + tid * 4));
        }
        asm volatile("cp.async.commit_group;\n");
    };

    issue_chunk(0);

    // warp-resident top-32 state for 4 queries (warp wid owns q = 4*wid+r)
    unsigned cu[4]; int ci[4]; float thr[4]; unsigned thrU[4];
    const unsigned NEGINF_U = fenc(-INFINITY);
#pragma unroll
    for (int r = 0; r < 4; r++) {
        cu[r] = NEGINF_U; ci[r] = 0; thr[r] = -INFINITY; thrU[r] = NEGINF_U;
    }

    const float* qb = sQ + (4 * wid) * MUS;

    for (int ch = 0; ch < NCHUNK; ++ch) {
        asm volatile("cp.async.wait_group 0;\n");
        __syncthreads();   // buf[ch&1]+hm2 visible; prior GEMM reads complete
        if (ch + 1 < NCHUNK) issue_chunk(ch + 1);  // overlaps with GEMM below

        const float* mb = sMu + (ch & 1) * (CT * MUS);
        const float* hb = sHm2 + (ch & 1) * CT;

        // ---- GEMM: 4q (warp's own) x 4c (lane+32s) per thread, f32x2 FMA ----
        unsigned long long acc[4][4];
#pragma unroll
        for (int r = 0; r < 4; r++)
#pragma unroll
            for (int s = 0; s < 4; s++) acc[r][s] = 0ull;

        const float* mrow = mb + lane * MUS;
#pragma unroll
        for (int k = 0; k < DK; k += 4) {
            ulonglong2 qv[4], cvv[4];
#pragma unroll
            for (int r = 0; r < 4; r++)
                qv[r] = *reinterpret_cast<const ulonglong2*>(qb + r * MUS + k);
#pragma unroll
            for (int s = 0; s < 4; s++)
                cvv[s] = *reinterpret_cast<const ulonglong2*>(mrow + (32 * s) * MUS + k);
#pragma unroll
            for (int r = 0; r < 4; r++)
#pragma unroll
                for (int s = 0; s < 4; s++) {
                    asm("fma.rn.f32x2 %0, %1, %2, %0;"
                        : "+l"(acc[r][s]) : "l"(qv[r].x), "l"(cvv[s].x));
                    asm("fma.rn.f32x2 %0, %1, %2, %0;"
                        : "+l"(acc[r][s]) : "l"(qv[r].y), "l"(cvv[s].y));
                }
        }

        // scores: s' = q.mu - 0.5||mu||^2 (selection metric, softmax-equivalent)
        float sc[4][4];
        float h[4];
#pragma unroll
        for (int s = 0; s < 4; s++) h[s] = hb[lane + 32 * s];
#pragma unroll
        for (int r = 0; r < 4; r++)
#pragma unroll
            for (int s = 0; s < 4; s++) {
                float2 f = *reinterpret_cast<float2*>(&acc[r][s]);
                sc[r][s] = f.x + f.y - h[s];
            }

        // ---- streaming top-32, in registers ----
        const int base = ch * CT;
#pragma unroll
        for (int r = 0; r < 4; r++) {
            float vm = fmaxf(fmaxf(sc[r][0], sc[r][1]), fmaxf(sc[r][2], sc[r][3]));
            if (__ballot_sync(FULLMASK, vm > thr[r])) {
#pragma unroll
                for (int s = 0; s < 4; s++) {
                    float v = sc[r][s];
                    unsigned m = __ballot_sync(FULLMASK, v > thr[r]);
                    int segbase = base + 32 * s;
                    while (m) {
                        int src = __ffs(m) - 1;
                        m &= m - 1;
                        float nv = __shfl_sync(FULLMASK, v, src);
                        if (nv > thr[r]) {
                            unsigned bl = __ballot_sync(FULLMASK, cu[r] == thrU[r]);
                            int ml = __ffs(bl) - 1;
                            if (lane == ml) { cu[r] = fenc(nv); ci[r] = segbase + src; }
                            thrU[r] = redux_min_u32(cu[r]);
                            thr[r]  = fdec(thrU[r]);
                        }
                    }
                }
            }
        }
    }

    // ---- publish top-32 per query ----
#pragma unroll
    for (int r = 0; r < 4; r++) {
        int q = 4 * wid + r;
        sTopV[q * 32 + lane] = fdec(cu[r]);
        sTopI[q * 32 + lane] = ci[r];
    }
    __syncthreads();

    const float sigma  = sig[0];
    const float inv_s2 = 1.f / (sigma * sigma);
    const float bgate  = Wgb[0];
    const float gw     = gpw[0];

    float* myW = sScr + wid * 64;
    int*   myI = reinterpret_cast<int*>(myW + 32);

    // ---- epilogue: softmax + gathers + gate; warp w handles q = w + 8*round
#pragma unroll
    for (int round = 0; round < 4; ++round) {
        int q  = wid + 8 * round;
        int qg = q0 + q;

        float sv  = sTopV[q * 32 + lane];
        int   idx = sTopI[q * 32 + lane];
        float s = sv * inv_s2;
        float mx = s;
#pragma unroll
        for (int off = 16; off; off >>= 1)
            mx = fmaxf(mx, __shfl_xor_sync(FULLMASK, mx, off));
        float e = __expf(s - mx);
        float se = e;
#pragma unroll
        for (int off = 16; off; off >>= 1)
            se += __shfl_xor_sync(FULLMASK, se, off);
        float wgt = e / se;

        myW[lane] = wgt;
        myI[lane] = idx;
        __syncwarp();

        // r_V: lane owns dims [4*lane, 4*lane+4)
        float4 acc = make_float4(0.f, 0.f, 0.f, 0.f);
#pragma unroll 4
        for (int k = 0; k < 32; k++) {
            float wk = myW[k];
            size_t row = (size_t)myI[k];
            float4 v = reinterpret_cast<const float4*>(V + row * 128)[lane];
            acc.x += wk * v.x; acc.y += wk * v.y;
            acc.z += wk * v.z; acc.w += wk * v.w;
        }

        // r_E (4 dims)
        float re = 0.f;
        if (lane < 4) {
            for (int k = 0; k < 32; k++)
                re += myW[k] * E[(size_t)myI[k] * 4 + lane];
        }

        // gate: sigmoid( x.W1 + rV.W2 + b + gpw * g_prior )
        const float4 wv = reinterpret_cast<const float4*>(Wg + 256)[lane];
        float tot = acc.x * wv.x + acc.y * wv.y + acc.z * wv.z + acc.w * wv.w;
        const float* xq = x + (size_t)qg * 256;
#pragma unroll
        for (int u = 0; u < 8; u++) {
            int t = lane + 32 * u;
            tot += xq[t] * Wg[t];
        }
#pragma unroll
        for (int off = 16; off; off >>= 1)
            tot += __shfl_xor_sync(FULLMASK, tot, off);

        reinterpret_cast<float4*>(out + RV_OFF + (size_t)qg * 128)[lane] = acc;
        if (lane < 4) out[RE_OFF + (size_t)qg * 4 + lane] = re;
        if (lane == 0) {
            float z = tot + bgate + gw * g_prior[qg];
            out[G_OFF + qg] = 1.f / (1.f + __expf(-z));
        }
        __syncwarp();
    }
}

extern "C" void kernel_launch(void* const* d_in, const int* in_sizes, int n_in,
                              void* d_out, int out_size) {
    (void)in_sizes; (void)n_in; (void)out_size;
    const float* x   = (const float*)d_in[0];
    const float* qt  = (const float*)d_in[1];
    const float* gp  = (const float*)d_in[2];
    const float* mu  = (const float*)d_in[3];
    const float* V   = (const float*)d_in[4];
    const float* E   = (const float*)d_in[5];
    const float* sg  = (const float*)d_in[6];
    const float* Wg  = (const float*)d_in[7];
    const float* Wb  = (const float*)d_in[8];
    const float* gw  = (const float*)d_in[9];

    hm2_kernel<<<NC / 256, 256>>>(mu);

    const int smem_bytes = SMEM_FLOATS * 4;
    cudaFuncSetAttribute(ma_kernel, cudaFuncAttributeMaxDynamicSharedMemorySize,
                         smem_bytes);
    ma_kernel<<<NQ / QT, 256, smem_bytes>>>(x, qt, gp, mu, V, E, sg, Wg, Wb, gw,
                                            (float*)d_out);
}